// round 6
// baseline (speedup 1.0000x reference)
#include <cuda_runtime.h>
#include <cuda_fp16.h>
#include <math.h>

// Persistent-kernel LSTM decoder. B=64, H=1024, L=2, T=128.
// 128 CTAs (1/SM). Per layer-phase: ONE merged 32-chunk K-loop
// (chunks 0-15: h@Whh resident SMEM weights; 16-31: x@Wih streamed),
// ring-4 / depth-3 cp.async pipeline, one __syncthreads per chunk.
// Grid-barrier wait is triggered when the prefetcher reaches chunk 16
// (staged at iter 13) => hidden behind 13 chunks of recurrent compute.
// (R6 = R5 resubmit: prior bench was an infra failure, kernel unchanged.)

#define BATCH   64
#define HID     1024
#define TSTEPS  128
#define NCTA    128
#define THREADS 256
#define KC      64     // K per chunk
#define SA2     72     // ring buffer row stride (halfs) = KC + 8
#define SR      1032   // resident weight row stride (halfs)
#define NCH     32     // chunks per phase (16 h + 16 x)

// ---------------- device globals (pre-permuted fp16 weights + state) -------
__device__ __half g_Wih_p[2 * NCTA * 32 * HID];   // [l][cta][pn][k]
__device__ __half g_Whh_p[2 * NCTA * 32 * HID];
__device__ __half g_Wfc_p[NCTA * 8 * HID];        // [cta][u][k]
__device__ __half g_hbuf[4 * BATCH * HID];        // [l*2+parity][b][h]
__device__ __half g_x0[BATCH * HID];
__device__ unsigned g_bar;

// ---------------- small asm helpers ---------------------------------------
__device__ __forceinline__ unsigned sptr(const void* p) {
    return (unsigned)__cvta_generic_to_shared(p);
}
__device__ __forceinline__ void cp16(void* s, const void* g) {      // weights (.ca)
    asm volatile("cp.async.ca.shared.global [%0], [%1], 16;" :: "r"(sptr(s)), "l"(g));
}
__device__ __forceinline__ void cp16cg(void* s, const void* g) {    // acts (.cg)
    asm volatile("cp.async.cg.shared.global [%0], [%1], 16;" :: "r"(sptr(s)), "l"(g));
}
__device__ __forceinline__ void cp_commit() {
    asm volatile("cp.async.commit_group;");
}
template<int N> __device__ __forceinline__ void cp_wait() {
    asm volatile("cp.async.wait_group %0;" :: "n"(N));
}
__device__ __forceinline__ void ldsm_x4(unsigned &r0, unsigned &r1, unsigned &r2, unsigned &r3, unsigned a) {
    asm volatile("ldmatrix.sync.aligned.m8n8.x4.shared.b16 {%0,%1,%2,%3}, [%4];"
                 : "=r"(r0), "=r"(r1), "=r"(r2), "=r"(r3) : "r"(a));
}
__device__ __forceinline__ void ldsm_x2(unsigned &r0, unsigned &r1, unsigned a) {
    asm volatile("ldmatrix.sync.aligned.m8n8.x2.shared.b16 {%0,%1}, [%2];"
                 : "=r"(r0), "=r"(r1) : "r"(a));
}
__device__ __forceinline__ void hmma(float d[4], unsigned a0, unsigned a1, unsigned a2, unsigned a3,
                                     unsigned b0, unsigned b1) {
    asm volatile("mma.sync.aligned.m16n8k16.row.col.f32.f16.f16.f32 "
                 "{%0,%1,%2,%3},{%4,%5,%6,%7},{%8,%9},{%0,%1,%2,%3};"
                 : "+f"(d[0]), "+f"(d[1]), "+f"(d[2]), "+f"(d[3])
                 : "r"(a0), "r"(a1), "r"(a2), "r"(a3), "r"(b0), "r"(b1));
}
__device__ __forceinline__ float sig_(float x) { return 1.0f / (1.0f + __expf(-x)); }

// ---------------- prep kernels ---------------------------------------------
// permuted col index pn -> (gate, unit):
//   nn=pn&15; half=nn>>3; a=(nn&7)>>1; s=nn&1; gate=half*2+s; unit=(pn>>4)*4+a
__global__ void prep_gatew(const float* __restrict__ Wih, const float* __restrict__ Whh) {
    const int total = 2 * NCTA * 32 * HID;
    for (int e = blockIdx.x * blockDim.x + threadIdx.x; e < total; e += gridDim.x * blockDim.x) {
        int k = e & (HID - 1);
        int pn = (e >> 10) & 31;
        int cta = (e >> 15) & (NCTA - 1);
        int l = e >> 22;
        int nn = pn & 15, half = nn >> 3, a = (nn & 7) >> 1, s = nn & 1;
        int gate = half * 2 + s, unit = (pn >> 4) * 4 + a;
        size_t src = (size_t)l * 4 * HID * HID + (size_t)(gate * HID + cta * 8 + unit) * HID + k;
        g_Wih_p[e] = __float2half_rn(Wih[src]);
        g_Whh_p[e] = __float2half_rn(Whh[src]);
    }
}
__global__ void prep_misc(const float* __restrict__ h0, const float* __restrict__ Wfc) {
    int i = blockIdx.x * blockDim.x + threadIdx.x;
    int stride = gridDim.x * blockDim.x;
    for (int e = i; e < NCTA * 8 * HID; e += stride) {
        int k = e & (HID - 1);
        int u = (e >> 10) & 7;
        int cta = e >> 13;
        g_Wfc_p[e] = __float2half_rn(Wfc[(size_t)(cta * 8 + u) * HID + k]);
    }
    for (int e = i; e < BATCH * HID; e += stride) g_x0[e] = __float2half_rn(h0[e]);
    for (int e = i; e < 4 * BATCH * HID; e += stride) g_hbuf[e] = __float2half_rn(0.0f);
    if (i == 0) g_bar = 0;
}

// ---------------- split grid barrier ---------------------------------------
__device__ __forceinline__ void gbar_arrive() {
    __threadfence();
    __syncthreads();
    if (threadIdx.x == 0) atomicAdd(&g_bar, 1u);
}
__device__ __forceinline__ void gbar_wait(unsigned target) {
    if (threadIdx.x == 0) {
        unsigned v;
        do {
            asm volatile("ld.acquire.gpu.u32 %0, [%1];" : "=r"(v) : "l"(&g_bar));
        } while (v < target);
    }
    __syncthreads();
}

// ---------------- staging (KC=64 chunks) ------------------------------------
__device__ __forceinline__ void stage_act64(__half* dst, const __half* src, int k0, int tid) {
    #pragma unroll
    for (int i = 0; i < 2; i++) {
        int e = tid + i * THREADS;          // 512 ops: 64 rows x 8 segs
        int r = e >> 3, sg = e & 7;
        cp16cg(dst + r * SA2 + sg * 8, src + r * HID + k0 + sg * 8);
    }
}
__device__ __forceinline__ void stage_w64(__half* dst, const __half* src, int k0, int tid) {
    int r = tid >> 3, sg = tid & 7;         // 256 ops: 32 rows x 8 segs
    cp16(dst + r * SA2 + sg * 8, src + r * HID + k0 + sg * 8);
}

// ---------------- main persistent kernel ------------------------------------
__global__ __launch_bounds__(THREADS, 1) void lstm_persist(
    const float* __restrict__ bih, const float* __restrict__ bhh,
    const float* __restrict__ bfc, float* __restrict__ out)
{
    extern __shared__ __align__(16) unsigned char smem_raw[];
    __half* whhS  = (__half*)smem_raw;            // [2][32][SR]
    __half* wfcS  = whhS + 2 * 32 * SR;           // [8][SR]
    __half* xbufS = wfcS + 8 * SR;                // [4][64][SA2] act ring
    __half* wbufS = xbufS + 4 * 64 * SA2;         // [4][32][SA2] Wih ring
    float*  cS    = (float*)(wbufS + 4 * 32 * SA2);// [2][64][8]
    float*  biasS = cS + 2 * 64 * 8;              // [2][32]
    float*  fcbS  = biasS + 64;                   // [8]
    float*  redS  = fcbS + 8;                     // [4][32][4]

    const int tid  = threadIdx.x;
    const int warp = tid >> 5;
    const int lane = tid & 31;
    const int wm   = warp & 3;     // M-tile
    const int wn   = warp >> 2;    // N-tile (unit group)
    const int cta  = blockIdx.x;
    const int j0   = cta * 8;

    // ---- load resident weights (Whh both layers + Wfc slice) ----
    for (int l = 0; l < 2; l++) {
        const __half* src = g_Whh_p + (size_t)(l * NCTA + cta) * 32 * HID;
        for (int i = 0; i < 16; i++) {
            int e = tid + i * THREADS;      // 32 rows x 128 segs
            int r = e >> 7, sg = e & 127;
            cp16(whhS + l * 32 * SR + r * SR + sg * 8, src + r * HID + sg * 8);
        }
    }
    {
        const __half* src = g_Wfc_p + (size_t)cta * 8 * HID;
        for (int i = 0; i < 4; i++) {
            int e = tid + i * THREADS;      // 8 rows x 128 segs
            int r = e >> 7, sg = e & 127;
            cp16(wfcS + r * SR + sg * 8, src + r * HID + sg * 8);
        }
    }
    cp_commit();
    // ---- biases / cell state ----
    if (tid < 64) {
        int l = tid >> 5, pn = tid & 31;
        int nn = pn & 15, half = nn >> 3, a = (nn & 7) >> 1, s = nn & 1;
        int gate = half * 2 + s, unit = (pn >> 4) * 4 + a;
        int row = gate * HID + j0 + unit;
        biasS[l * 32 + pn] = bih[l * 4 * HID + row] + bhh[l * 4 * HID + row];
    }
    if (tid < 8) fcbS[tid] = bfc[j0 + tid];
    #pragma unroll
    for (int i = 0; i < 4; i++) cS[tid + i * THREADS] = 0.0f;
    cp_wait<0>();
    __syncthreads();

    // per-lane fragment offsets (bytes)
    const unsigned xoff = ((wm * 16 + (lane & 15)) * SA2 + (lane >> 4) * 8) * 2;
    const unsigned woff = ((wn * 16 + (lane & 15)) * SA2 + (lane >> 4) * 8) * 2;
    const unsigned xring = sptr(xbufS);
    const unsigned wring = sptr(wbufS);
    const unsigned XBUF = 64 * SA2 * 2;   // act ring buffer stride (bytes)
    const unsigned WBUF = 32 * SA2 * 2;   // Wih ring buffer stride
    const unsigned whAl[2] = {
        sptr(whhS) + ((wn * 16 + (lane & 15)) * SR + (lane >> 4) * 8) * 2,
        sptr(whhS) + ((32 + wn * 16 + (lane & 15)) * SR + (lane >> 4) * 8) * 2 };
    const unsigned fcA = sptr(wfcS) + (((lane & 7)) * SR + ((lane >> 3) & 1) * 8) * 2;

    unsigned barTarget = 0;
    const int r = lane >> 2, a4 = lane & 3;
    const int uloc = wn * 4 + a4;

    for (int t = 0; t < TSTEPS; t++) {
        const int p = t & 1, q = p ^ 1;
        #pragma unroll 1
        for (int l = 0; l < 2; l++) {
            const __half* xsrc = (l == 0)
                ? ((t == 0) ? g_x0 : g_hbuf + (2 + q) * BATCH * HID)
                : g_hbuf + (0 + p) * BATCH * HID;
            const __half* hsrc = g_hbuf + (l * 2 + q) * BATCH * HID;
            __half* hdst = g_hbuf + (l * 2 + p) * BATCH * HID;
            const __half* wsrc = g_Wih_p + (size_t)(l * NCTA + cta) * 32 * HID;
            const bool fc_phase = (l == 0) && (t > 0);

            float acc0[2][4] = {{0,0,0,0},{0,0,0,0}};
            float acc1[2][4] = {{0,0,0,0},{0,0,0,0}};
            float fca[4] = {0, 0, 0, 0};

            // ---- pipeline prologue: stage h-chunks 0,1,2 ----
            stage_act64(xbufS + 0 * 64 * SA2, hsrc, 0 * KC, tid); cp_commit();
            stage_act64(xbufS + 1 * 64 * SA2, hsrc, 1 * KC, tid); cp_commit();
            stage_act64(xbufS + 2 * 64 * SA2, hsrc, 2 * KC, tid); cp_commit();

            // ---- merged 32-chunk loop (16 h@Whh, then 16 x@Wih [+FC]) ----
            #pragma unroll 1
            for (int c = 0; c < NCH; c++) {
                cp_wait<2>();
                __syncthreads();
                const int cs = c + 3;
                if (cs < NCH) {
                    if (cs == 16) gbar_wait(barTarget);   // x becomes legal here
                    const __half* asrc = (cs < 16) ? hsrc : xsrc;
                    stage_act64(xbufS + (cs & 3) * 64 * SA2, asrc, (cs & 15) * KC, tid);
                    if (cs >= 16)
                        stage_w64(wbufS + (cs & 3) * 32 * SA2, wsrc, (cs - 16) * KC, tid);
                }
                cp_commit();

                const unsigned xb = xring + (c & 3) * XBUF + xoff;
                const unsigned wbase = (c < 16)
                    ? whAl[l] + c * (KC * 2)
                    : wring + (c & 3) * WBUF + woff;
                const bool fcrun = fc_phase && (c >= 16);
                const unsigned fb = fcA + (c - 16) * (KC * 2);

                #pragma unroll
                for (int k16 = 0; k16 < KC / 16; k16++) {
                    const int e = k16 & 1;
                    unsigned a0, a1, a2, a3, b0, b1, b2, b3;
                    ldsm_x4(a0, a1, a2, a3, xb + k16 * 32);
                    ldsm_x4(b0, b1, b2, b3, wbase + k16 * 32);
                    hmma(acc0[e], a0, a1, a2, a3, b0, b2);
                    hmma(acc1[e], a0, a1, a2, a3, b1, b3);
                    if (fcrun && e == wn) {
                        unsigned f0, f1;
                        ldsm_x2(f0, f1, fb + k16 * 32);
                        hmma(fca, a0, a1, a2, a3, f0, f1);
                    }
                }
            }

            // ===== epilogue: register-local cell update =====
            float* crow = cS + l * 64 * 8;
            #pragma unroll
            for (int rp = 0; rp < 2; rp++) {
                int b = wm * 16 + r + rp * 8;
                int k = rp * 2;
                float iv = acc0[0][k+0] + acc0[1][k+0] + biasS[l * 32 + wn * 16 + a4 * 2 + 0];
                float fv = acc0[0][k+1] + acc0[1][k+1] + biasS[l * 32 + wn * 16 + a4 * 2 + 1];
                float gv = acc1[0][k+0] + acc1[1][k+0] + biasS[l * 32 + wn * 16 + 8 + a4 * 2 + 0];
                float ov = acc1[0][k+1] + acc1[1][k+1] + biasS[l * 32 + wn * 16 + 8 + a4 * 2 + 1];
                float cn = sig_(fv) * crow[b * 8 + uloc] + sig_(iv) * tanhf(gv);
                crow[b * 8 + uloc] = cn;
                hdst[b * HID + j0 + uloc] = __float2half_rn(sig_(ov) * tanhf(cn));
            }
            if (fc_phase) {
                if (wn == 1) {
                    #pragma unroll
                    for (int i = 0; i < 4; i++) redS[(wm * 32 + lane) * 4 + i] = fca[i];
                }
                __syncthreads();
                if (wn == 0) {
                    float* op = out + (size_t)(t - 1) * BATCH * HID;
                    #pragma unroll
                    for (int rp = 0; rp < 2; rp++) {
                        int b = wm * 16 + r + rp * 8;
                        int k = rp * 2;
                        float v0 = fca[k+0] + redS[(wm * 32 + lane) * 4 + k + 0] + fcbS[a4 * 2 + 0];
                        float v1 = fca[k+1] + redS[(wm * 32 + lane) * 4 + k + 1] + fcbS[a4 * 2 + 1];
                        op[b * HID + j0 + a4 * 2 + 0] = v0;
                        op[b * HID + j0 + a4 * 2 + 1] = v1;
                    }
                }
            }
            gbar_arrive();
            barTarget += NCTA;
        }
    }

    // ===== final FC for t = T-1 (x = h1 written at t=127, parity 1) =====
    {
        gbar_wait(barTarget);
        const __half* xsrc = g_hbuf + (2 + 1) * BATCH * HID;
        float fca[4] = {0, 0, 0, 0};
        stage_act64(xbufS + 0 * 64 * SA2, xsrc, 0 * KC, tid); cp_commit();
        stage_act64(xbufS + 1 * 64 * SA2, xsrc, 1 * KC, tid); cp_commit();
        stage_act64(xbufS + 2 * 64 * SA2, xsrc, 2 * KC, tid); cp_commit();
        #pragma unroll 1
        for (int c = 0; c < 16; c++) {
            cp_wait<2>();
            __syncthreads();
            if (c + 3 < 16)
                stage_act64(xbufS + ((c + 3) & 3) * 64 * SA2, xsrc, (c + 3) * KC, tid);
            cp_commit();
            const unsigned xb = xring + (c & 3) * XBUF + xoff;
            #pragma unroll
            for (int k16 = 0; k16 < KC / 16; k16++) {
                if ((k16 & 1) == wn) {
                    unsigned a0, a1, a2, a3, f0, f1;
                    ldsm_x4(a0, a1, a2, a3, xb + k16 * 32);
                    ldsm_x2(f0, f1, fcA + (c * KC + k16 * 16) * 2);
                    hmma(fca, a0, a1, a2, a3, f0, f1);
                }
            }
        }
        __syncthreads();
        if (wn == 1) {
            #pragma unroll
            for (int i = 0; i < 4; i++) redS[(wm * 32 + lane) * 4 + i] = fca[i];
        }
        __syncthreads();
        if (wn == 0) {
            float* op = out + (size_t)(TSTEPS - 1) * BATCH * HID;
            #pragma unroll
            for (int rp = 0; rp < 2; rp++) {
                int b = wm * 16 + r + rp * 8;
                int k = rp * 2;
                float v0 = fca[k+0] + redS[(wm * 32 + lane) * 4 + k + 0] + fcbS[a4 * 2 + 0];
                float v1 = fca[k+1] + redS[(wm * 32 + lane) * 4 + k + 1] + fcbS[a4 * 2 + 1];
                op[b * HID + j0 + a4 * 2 + 0] = v0;
                op[b * HID + j0 + a4 * 2 + 1] = v1;
            }
        }
    }
}

// ---------------- host launch -----------------------------------------------
extern "C" void kernel_launch(void* const* d_in, const int* in_sizes, int n_in,
                              void* d_out, int out_size) {
    const float* h0  = (const float*)d_in[0];
    const float* Wih = (const float*)d_in[1];
    const float* Whh = (const float*)d_in[2];
    const float* bih = (const float*)d_in[3];
    const float* bhh = (const float*)d_in[4];
    const float* Wfc = (const float*)d_in[5];
    const float* bfc = (const float*)d_in[6];
    float* out = (float*)d_out;

    const int smem = (2 * 32 * SR + 8 * SR + 4 * 64 * SA2 + 4 * 32 * SA2) * 2
                   + (2 * 64 * 8 + 64 + 8 + 4 * 32 * 4) * 4;
    cudaFuncSetAttribute(lstm_persist, cudaFuncAttributeMaxDynamicSharedMemorySize, smem);

    prep_gatew<<<2048, 256>>>(Wih, Whh);
    prep_misc<<<512, 256>>>(h0, Wfc);
    lstm_persist<<<NCTA, THREADS, smem>>>(bih, bhh, bfc, out);
}

// round 7
// speedup vs baseline: 1.2388x; 1.2388x over previous
#include <cuda_runtime.h>
#include <cuda_fp16.h>
#include <math.h>

// Persistent-kernel LSTM decoder. B=64, H=1024, L=2, T=128.
// 128 CTAs (1/SM), split arrive/wait grid barrier between layer phases.
// R7 = R4 baseline (best: 3061us) + per-CTA K-chunk staggering
// (spreads L2 slice load: CTA i does chunks (kc+i)&7) + single prep kernel.

#define BATCH   64
#define HID     1024
#define TSTEPS  128
#define NCTA    128
#define THREADS 256
#define SA      136    // streamed act chunk row stride (halfs)
#define SW      136    // streamed weight chunk row stride (halfs)
#define SR      1032   // resident weight row stride (halfs)
#define KC      128    // K chunk

// ---------------- device globals (pre-permuted fp16 weights + state) -------
__device__ __half g_Wih_p[2 * NCTA * 32 * HID];   // [l][cta][pn][k]
__device__ __half g_Whh_p[2 * NCTA * 32 * HID];
__device__ __half g_Wfc_p[NCTA * 8 * HID];        // [cta][u][k]
__device__ __half g_hbuf[4 * BATCH * HID];        // [l*2+parity][b][h]
__device__ __half g_x0[BATCH * HID];
__device__ unsigned g_bar;

// ---------------- small asm helpers ---------------------------------------
__device__ __forceinline__ unsigned sptr(const void* p) {
    return (unsigned)__cvta_generic_to_shared(p);
}
__device__ __forceinline__ void cp16(void* s, const void* g) {      // weights (.ca)
    asm volatile("cp.async.ca.shared.global [%0], [%1], 16;" :: "r"(sptr(s)), "l"(g));
}
__device__ __forceinline__ void cp16cg(void* s, const void* g) {    // acts (.cg)
    asm volatile("cp.async.cg.shared.global [%0], [%1], 16;" :: "r"(sptr(s)), "l"(g));
}
__device__ __forceinline__ void cp_commit() {
    asm volatile("cp.async.commit_group;");
}
template<int N> __device__ __forceinline__ void cp_wait() {
    asm volatile("cp.async.wait_group %0;" :: "n"(N));
}
__device__ __forceinline__ void ldsm_x4(unsigned &r0, unsigned &r1, unsigned &r2, unsigned &r3, unsigned a) {
    asm volatile("ldmatrix.sync.aligned.m8n8.x4.shared.b16 {%0,%1,%2,%3}, [%4];"
                 : "=r"(r0), "=r"(r1), "=r"(r2), "=r"(r3) : "r"(a));
}
__device__ __forceinline__ void ldsm_x2(unsigned &r0, unsigned &r1, unsigned a) {
    asm volatile("ldmatrix.sync.aligned.m8n8.x2.shared.b16 {%0,%1}, [%2];"
                 : "=r"(r0), "=r"(r1) : "r"(a));
}
__device__ __forceinline__ void hmma(float d[4], unsigned a0, unsigned a1, unsigned a2, unsigned a3,
                                     unsigned b0, unsigned b1) {
    asm volatile("mma.sync.aligned.m16n8k16.row.col.f32.f16.f16.f32 "
                 "{%0,%1,%2,%3},{%4,%5,%6,%7},{%8,%9},{%0,%1,%2,%3};"
                 : "+f"(d[0]), "+f"(d[1]), "+f"(d[2]), "+f"(d[3])
                 : "r"(a0), "r"(a1), "r"(a2), "r"(a3), "r"(b0), "r"(b1));
}
__device__ __forceinline__ float sig_(float x) { return 1.0f / (1.0f + __expf(-x)); }

// ---------------- single merged prep kernel ---------------------------------
// permuted col index pn -> (gate, unit):
//   nn=pn&15; half=nn>>3; a=(nn&7)>>1; s=nn&1; gate=half*2+s; unit=(pn>>4)*4+a
__global__ void prep_all(const float* __restrict__ Wih, const float* __restrict__ Whh,
                         const float* __restrict__ h0,  const float* __restrict__ Wfc) {
    int i = blockIdx.x * blockDim.x + threadIdx.x;
    int stride = gridDim.x * blockDim.x;
    const int totalG = 2 * NCTA * 32 * HID;
    for (int e = i; e < totalG; e += stride) {
        int k = e & (HID - 1);
        int pn = (e >> 10) & 31;
        int cta = (e >> 15) & (NCTA - 1);
        int l = e >> 22;
        int nn = pn & 15, half = nn >> 3, a = (nn & 7) >> 1, s = nn & 1;
        int gate = half * 2 + s, unit = (pn >> 4) * 4 + a;
        size_t src = (size_t)l * 4 * HID * HID + (size_t)(gate * HID + cta * 8 + unit) * HID + k;
        g_Wih_p[e] = __float2half_rn(Wih[src]);
        g_Whh_p[e] = __float2half_rn(Whh[src]);
    }
    for (int e = i; e < NCTA * 8 * HID; e += stride) {
        int k = e & (HID - 1);
        int u = (e >> 10) & 7;
        int cta = e >> 13;
        g_Wfc_p[e] = __float2half_rn(Wfc[(size_t)(cta * 8 + u) * HID + k]);
    }
    for (int e = i; e < BATCH * HID; e += stride) g_x0[e] = __float2half_rn(h0[e]);
    for (int e = i; e < 4 * BATCH * HID; e += stride) g_hbuf[e] = __float2half_rn(0.0f);
    if (i == 0) g_bar = 0;
}

// ---------------- split grid barrier ---------------------------------------
__device__ __forceinline__ void gbar_arrive() {
    __threadfence();
    __syncthreads();
    if (threadIdx.x == 0) atomicAdd(&g_bar, 1u);
}
__device__ __forceinline__ void gbar_wait(unsigned target) {
    if (threadIdx.x == 0) {
        unsigned v;
        do {
            asm volatile("ld.acquire.gpu.u32 %0, [%1];" : "=r"(v) : "l"(&g_bar));
        } while (v < target);
    }
    __syncthreads();
}

// ---------------- staging ---------------------------------------------------
__device__ __forceinline__ void stage_act(__half* dst, const __half* src, int k0, int tid) {
    #pragma unroll
    for (int i = 0; i < 4; i++) {
        int e = tid + i * THREADS;          // 1024 ops: 64 rows x 16 segs
        int r = e >> 4, sg = e & 15;
        cp16cg(dst + r * SA + sg * 8, src + r * HID + k0 + sg * 8);
    }
}
__device__ __forceinline__ void stage_w(__half* dst, const __half* src, int k0, int tid) {
    #pragma unroll
    for (int i = 0; i < 2; i++) {
        int e = tid + i * THREADS;          // 512 ops: 32 rows x 16 segs
        int r = e >> 4, sg = e & 15;
        cp16(dst + r * SW + sg * 8, src + r * HID + k0 + sg * 8);
    }
}

// ---------------- main persistent kernel ------------------------------------
__global__ __launch_bounds__(THREADS, 1) void lstm_persist(
    const float* __restrict__ bih, const float* __restrict__ bhh,
    const float* __restrict__ bfc, float* __restrict__ out)
{
    extern __shared__ __align__(16) unsigned char smem_raw[];
    __half* whhS  = (__half*)smem_raw;            // [2][32][SR]
    __half* wfcS  = whhS + 2 * 32 * SR;           // [8][SR]
    __half* xbufS = wfcS + 8 * SR;                // [2][64][SA]
    __half* wbufS = xbufS + 2 * 64 * SA;          // [2][32][SW]
    float*  cS    = (float*)(wbufS + 2 * 32 * SW);// [2][64][8]
    float*  biasS = cS + 2 * 64 * 8;              // [2][32]
    float*  fcbS  = biasS + 64;                   // [8]
    float*  redS  = fcbS + 8;                     // [4][32][4]

    const int tid  = threadIdx.x;
    const int warp = tid >> 5;
    const int lane = tid & 31;
    const int wm   = warp & 3;     // M-tile
    const int wn   = warp >> 2;    // N-tile (unit group)
    const int cta  = blockIdx.x;
    const int j0   = cta * 8;
    const int coff = cta & 7;      // K-chunk stagger offset

    // ---- load resident weights (Whh both layers + Wfc slice) ----
    for (int l = 0; l < 2; l++) {
        const __half* src = g_Whh_p + (size_t)(l * NCTA + cta) * 32 * HID;
        for (int i = 0; i < 16; i++) {
            int e = tid + i * THREADS;      // 32 rows x 128 segs
            int r = e >> 7, sg = e & 127;
            cp16(whhS + l * 32 * SR + r * SR + sg * 8, src + r * HID + sg * 8);
        }
    }
    {
        const __half* src = g_Wfc_p + (size_t)cta * 8 * HID;
        for (int i = 0; i < 4; i++) {
            int e = tid + i * THREADS;      // 8 rows x 128 segs
            int r = e >> 7, sg = e & 127;
            cp16(wfcS + r * SR + sg * 8, src + r * HID + sg * 8);
        }
    }
    cp_commit();
    // ---- biases / cell state ----
    if (tid < 64) {
        int l = tid >> 5, pn = tid & 31;
        int nn = pn & 15, half = nn >> 3, a = (nn & 7) >> 1, s = nn & 1;
        int gate = half * 2 + s, unit = (pn >> 4) * 4 + a;
        int row = gate * HID + j0 + unit;
        biasS[l * 32 + pn] = bih[l * 4 * HID + row] + bhh[l * 4 * HID + row];
    }
    if (tid < 8) fcbS[tid] = bfc[j0 + tid];
    #pragma unroll
    for (int i = 0; i < 4; i++) cS[tid + i * THREADS] = 0.0f;
    cp_wait<0>();
    __syncthreads();

    // precomputed shared addresses (bytes)
    const unsigned xb0 = sptr(xbufS) + ((wm * 16 + (lane & 15)) * SA + (lane >> 4) * 8) * 2;
    const unsigned xb1 = xb0 + 64 * SA * 2;
    const unsigned wb0 = sptr(wbufS) + ((wn * 16 + (lane & 15)) * SW + (lane >> 4) * 8) * 2;
    const unsigned wb1 = wb0 + 32 * SW * 2;
    const unsigned whA[2] = {
        sptr(whhS) + ((wn * 16 + (lane & 15)) * SR + (lane >> 4) * 8) * 2,
        sptr(whhS) + ((32 + wn * 16 + (lane & 15)) * SR + (lane >> 4) * 8) * 2 };
    const unsigned fcA = sptr(wfcS) + (((lane & 7)) * SR + ((lane >> 3) & 1) * 8) * 2;

    unsigned barTarget = 0;
    const int r = lane >> 2, a4 = lane & 3;
    const int uloc = wn * 4 + a4;

    for (int t = 0; t < TSTEPS; t++) {
        const int p = t & 1, q = p ^ 1;
        #pragma unroll 1
        for (int l = 0; l < 2; l++) {
            const __half* xsrc = (l == 0)
                ? ((t == 0) ? g_x0 : g_hbuf + (2 + q) * BATCH * HID)
                : g_hbuf + (0 + p) * BATCH * HID;
            const __half* hsrc = g_hbuf + (l * 2 + q) * BATCH * HID;
            __half* hdst = g_hbuf + (l * 2 + p) * BATCH * HID;
            const __half* wsrc = g_Wih_p + (size_t)(l * NCTA + cta) * 32 * HID;
            const bool fc_phase = (l == 0) && (t > 0);

            float acc0[2][4] = {{0,0,0,0},{0,0,0,0}};
            float acc1[2][4] = {{0,0,0,0},{0,0,0,0}};
            float fca[4] = {0, 0, 0, 0};

            // ===== part A: h_rec @ Whh (resident weights; no barrier needed:
            //       hsrc was written two phases ago). Staggered chunk order.
            //       Also prefetch Wih for part B's first chunk.
            stage_act(xbufS, hsrc, ((0 + coff) & 7) * KC, tid);
            stage_w(wbufS, wsrc, ((0 + coff) & 7) * KC, tid);
            cp_commit();
            #pragma unroll 1
            for (int kc = 0; kc < HID / KC; kc++) {
                const int rc = (kc + coff) & 7;          // actual K-chunk
                if (kc + 1 < HID / KC) {
                    stage_act(xbufS + ((kc + 1) & 1) * 64 * SA, hsrc,
                              (((kc + 1) + coff) & 7) * KC, tid);
                    cp_commit();
                    cp_wait<1>();
                } else cp_wait<0>();
                __syncthreads();
                const unsigned xb = (kc & 1) ? xb1 : xb0;
                #pragma unroll
                for (int k16 = 0; k16 < KC / 16; k16++) {
                    const int e = k16 & 1;
                    unsigned a0, a1, a2, a3, b0, b1, b2, b3;
                    ldsm_x4(a0, a1, a2, a3, xb + k16 * 32);
                    ldsm_x4(b0, b1, b2, b3, whA[l] + (rc * KC + k16 * 16) * 2);
                    hmma(acc0[e], a0, a1, a2, a3, b0, b2);
                    hmma(acc1[e], a0, a1, a2, a3, b1, b3);
                }
                __syncthreads();
            }

            // ===== barrier wait (mostly satisfied already) =====
            gbar_wait(barTarget);

            // ===== part B: x @ Wih (streamed) + FC (k-split across wn) =====
            stage_act(xbufS, xsrc, ((0 + coff) & 7) * KC, tid);
            cp_commit();
            #pragma unroll 1
            for (int kc = 0; kc < HID / KC; kc++) {
                const int rc = (kc + coff) & 7;
                if (kc + 1 < HID / KC) {
                    stage_act(xbufS + ((kc + 1) & 1) * 64 * SA, xsrc,
                              (((kc + 1) + coff) & 7) * KC, tid);
                    stage_w(wbufS + ((kc + 1) & 1) * 32 * SW, wsrc,
                            (((kc + 1) + coff) & 7) * KC, tid);
                    cp_commit();
                    cp_wait<1>();
                } else cp_wait<0>();
                __syncthreads();
                const unsigned xb = (kc & 1) ? xb1 : xb0;
                const unsigned wb = (kc & 1) ? wb1 : wb0;
                #pragma unroll
                for (int k16 = 0; k16 < KC / 16; k16++) {
                    const int e = k16 & 1;
                    unsigned a0, a1, a2, a3, b0, b1, b2, b3;
                    ldsm_x4(a0, a1, a2, a3, xb + k16 * 32);
                    ldsm_x4(b0, b1, b2, b3, wb + k16 * 32);
                    hmma(acc0[e], a0, a1, a2, a3, b0, b2);
                    hmma(acc1[e], a0, a1, a2, a3, b1, b3);
                    if (fc_phase && e == wn) {
                        unsigned f0, f1;
                        ldsm_x2(f0, f1, fcA + (rc * KC + k16 * 16) * 2);
                        hmma(fca, a0, a1, a2, a3, f0, f1);
                    }
                }
                __syncthreads();
            }

            // ===== epilogue: register-local cell update =====
            float* crow = cS + l * 64 * 8;
            #pragma unroll
            for (int rp = 0; rp < 2; rp++) {
                int b = wm * 16 + r + rp * 8;
                int k = rp * 2;
                float iv = acc0[0][k+0] + acc0[1][k+0] + biasS[l * 32 + wn * 16 + a4 * 2 + 0];
                float fv = acc0[0][k+1] + acc0[1][k+1] + biasS[l * 32 + wn * 16 + a4 * 2 + 1];
                float gv = acc1[0][k+0] + acc1[1][k+0] + biasS[l * 32 + wn * 16 + 8 + a4 * 2 + 0];
                float ov = acc1[0][k+1] + acc1[1][k+1] + biasS[l * 32 + wn * 16 + 8 + a4 * 2 + 1];
                float cn = sig_(fv) * crow[b * 8 + uloc] + sig_(iv) * tanhf(gv);
                crow[b * 8 + uloc] = cn;
                hdst[b * HID + j0 + uloc] = __float2half_rn(sig_(ov) * tanhf(cn));
            }
            if (fc_phase) {
                if (wn == 1) {
                    #pragma unroll
                    for (int i = 0; i < 4; i++) redS[(wm * 32 + lane) * 4 + i] = fca[i];
                }
                __syncthreads();
                if (wn == 0) {
                    float* op = out + (size_t)(t - 1) * BATCH * HID;
                    #pragma unroll
                    for (int rp = 0; rp < 2; rp++) {
                        int b = wm * 16 + r + rp * 8;
                        int k = rp * 2;
                        float v0 = fca[k+0] + redS[(wm * 32 + lane) * 4 + k + 0] + fcbS[a4 * 2 + 0];
                        float v1 = fca[k+1] + redS[(wm * 32 + lane) * 4 + k + 1] + fcbS[a4 * 2 + 1];
                        op[b * HID + j0 + a4 * 2 + 0] = v0;
                        op[b * HID + j0 + a4 * 2 + 1] = v1;
                    }
                }
            }
            gbar_arrive();
            barTarget += NCTA;
        }
    }

    // ===== final FC for t = T-1 (x = h1 written at t=127, parity 1) =====
    {
        gbar_wait(barTarget);
        const __half* xsrc = g_hbuf + (2 + 1) * BATCH * HID;
        float fca[4] = {0, 0, 0, 0};
        stage_act(xbufS, xsrc, ((0 + coff) & 7) * KC, tid);
        cp_commit();
        #pragma unroll 1
        for (int kc = 0; kc < HID / KC; kc++) {
            const int rc = (kc + coff) & 7;
            if (kc + 1 < HID / KC) {
                stage_act(xbufS + ((kc + 1) & 1) * 64 * SA, xsrc,
                          (((kc + 1) + coff) & 7) * KC, tid);
                cp_commit();
                cp_wait<1>();
            } else cp_wait<0>();
            __syncthreads();
            const unsigned xb = (kc & 1) ? xb1 : xb0;
            #pragma unroll
            for (int k16 = 0; k16 < KC / 16; k16++) {
                if ((k16 & 1) == wn) {
                    unsigned a0, a1, a2, a3, f0, f1;
                    ldsm_x4(a0, a1, a2, a3, xb + k16 * 32);
                    ldsm_x2(f0, f1, fcA + (rc * KC + k16 * 16) * 2);
                    hmma(fca, a0, a1, a2, a3, f0, f1);
                }
            }
            __syncthreads();
        }
        if (wn == 1) {
            #pragma unroll
            for (int i = 0; i < 4; i++) redS[(wm * 32 + lane) * 4 + i] = fca[i];
        }
        __syncthreads();
        if (wn == 0) {
            float* op = out + (size_t)(TSTEPS - 1) * BATCH * HID;
            #pragma unroll
            for (int rp = 0; rp < 2; rp++) {
                int b = wm * 16 + r + rp * 8;
                int k = rp * 2;
                float v0 = fca[k+0] + redS[(wm * 32 + lane) * 4 + k + 0] + fcbS[a4 * 2 + 0];
                float v1 = fca[k+1] + redS[(wm * 32 + lane) * 4 + k + 1] + fcbS[a4 * 2 + 1];
                op[b * HID + j0 + a4 * 2 + 0] = v0;
                op[b * HID + j0 + a4 * 2 + 1] = v1;
            }
        }
    }
}

// ---------------- host launch -----------------------------------------------
extern "C" void kernel_launch(void* const* d_in, const int* in_sizes, int n_in,
                              void* d_out, int out_size) {
    const float* h0  = (const float*)d_in[0];
    const float* Wih = (const float*)d_in[1];
    const float* Whh = (const float*)d_in[2];
    const float* bih = (const float*)d_in[3];
    const float* bhh = (const float*)d_in[4];
    const float* Wfc = (const float*)d_in[5];
    const float* bfc = (const float*)d_in[6];
    float* out = (float*)d_out;

    const int smem = (2 * 32 * SR + 8 * SR + 2 * 64 * SA + 2 * 32 * SW) * 2
                   + (2 * 64 * 8 + 64 + 8 + 4 * 32 * 4) * 4;
    cudaFuncSetAttribute(lstm_persist, cudaFuncAttributeMaxDynamicSharedMemorySize, smem);

    prep_all<<<2048, 256>>>(Wih, Whh, h0, Wfc);
    lstm_persist<<<NCTA, THREADS, smem>>>(bih, bhh, bfc, out);
}